// round 3
// baseline (speedup 1.0000x reference)
#include <cuda_runtime.h>
#include <math.h>

// ---------------------------------------------------------------------------
// GAT 2-layer forward, CSR aggregation, fused GEMM+attention-dots.
//   128 -> GAT(2x64, concat) -> elu -> GAT(1x64, mean) -> elu -> lin(64->16)
//   -> sigmoid.  Softmax max-shift skipped (logits O(+-6), shift-invariant).
// ---------------------------------------------------------------------------

#define NMAX 50176
#define EMAX 1200000
#define SCAN_TILE 1024

__device__ float g_h1  [NMAX * 128];
__device__ float g_as1 [NMAX * 2];
__device__ float g_ad1 [NMAX * 2];
__device__ float g_x2  [NMAX * 128];
__device__ float g_h2  [NMAX * 64];
__device__ float g_as2 [NMAX];
__device__ float g_ad2 [NMAX];
__device__ float g_o2  [NMAX * 64];
__device__ int   g_deg [NMAX];
__device__ int   g_rowptr[NMAX + 1];
__device__ int   g_cursor[NMAX];
__device__ int   g_col [EMAX];
__device__ int   g_bsum[256];
__device__ int   g_boff[256];

// ---------------------------------------------------------------------------
// Per-block int64-vs-int32 edge width detection (first 1024 entries, L2-hot).
// ---------------------------------------------------------------------------
__device__ __forceinline__ int detect_is64(const long long* __restrict__ ei,
                                           int E, int n) {
    __shared__ int bad;
    if (threadIdx.x == 0) bad = 0;
    __syncthreads();
    int cnt = E < 1024 ? E : 1024;
    int local = 0;
    for (int i = threadIdx.x; i < cnt; i += blockDim.x) {
        long long v = __ldg(&ei[i]);
        if (v < 0 || v >= (long long)n) local = 1;
    }
    if (__syncthreads_or(local)) return 0;
    return 1;
}

__global__ void zero_deg_kernel(int* __restrict__ deg, int n) {
    int i = blockIdx.x * blockDim.x + threadIdx.x;
    if (i < n) deg[i] = 0;
}

__global__ __launch_bounds__(256) void hist_kernel(const long long* __restrict__ ei,
                                                   int* __restrict__ deg, int E, int n) {
    int is64 = detect_is64(ei, E, n);
    int e = blockIdx.x * blockDim.x + threadIdx.x;
    if (e >= E) return;
    int dst = is64 ? (int)ei[E + e] : ((const int*)ei)[E + e];
    atomicAdd(&deg[dst], 1);
}

// ---------------------------------------------------------------------------
// 3-step exclusive scan of deg -> rowptr (+ cursor copy).
// ---------------------------------------------------------------------------
__global__ __launch_bounds__(256) void scan1_kernel(const int* __restrict__ deg,
                                                    int* __restrict__ bsum, int n) {
    __shared__ int sm[256];
    int base = blockIdx.x * SCAN_TILE;
    int s = 0;
    for (int i = base + threadIdx.x; i < base + SCAN_TILE && i < n; i += 256) s += deg[i];
    sm[threadIdx.x] = s;
    __syncthreads();
    for (int off = 128; off; off >>= 1) {
        if (threadIdx.x < off) sm[threadIdx.x] += sm[threadIdx.x + off];
        __syncthreads();
    }
    if (threadIdx.x == 0) bsum[blockIdx.x] = sm[0];
}

// Parallel scan of block sums (nb <= 64): one warp-ish block.
__global__ void scan2_kernel(const int* __restrict__ bsum, int* __restrict__ boff, int nb) {
    __shared__ int sm[64];
    int t = threadIdx.x;
    sm[t] = (t < nb) ? bsum[t] : 0;
    __syncthreads();
    for (int off = 1; off < 64; off <<= 1) {
        int v = (t >= off) ? sm[t - off] : 0;
        __syncthreads();
        sm[t] += v;
        __syncthreads();
    }
    if (t < nb) boff[t] = sm[t] - bsum[t];   // exclusive
}

__global__ __launch_bounds__(256) void scan3_kernel(const int* __restrict__ deg,
                                                    const int* __restrict__ boff,
                                                    int* __restrict__ rowptr,
                                                    int* __restrict__ cursor,
                                                    int n, int E) {
    __shared__ int sm[256];
    int base = blockIdx.x * SCAN_TILE;
    int tid = threadIdx.x;
    int v[4];
    int tsum = 0;
#pragma unroll
    for (int m = 0; m < 4; m++) {
        int i = base + tid * 4 + m;
        v[m] = (i < n) ? deg[i] : 0;
        tsum += v[m];
    }
    sm[tid] = tsum;
    __syncthreads();
    int run = tsum;
    for (int off = 1; off < 256; off <<= 1) {
        int t = (tid >= off) ? sm[tid - off] : 0;
        __syncthreads();
        sm[tid] += t;
        __syncthreads();
    }
    int excl = sm[tid] - run + boff[blockIdx.x];
#pragma unroll
    for (int m = 0; m < 4; m++) {
        int i = base + tid * 4 + m;
        if (i < n) { rowptr[i] = excl; cursor[i] = excl; }
        excl += v[m];
    }
    if (blockIdx.x == 0 && tid == 0) rowptr[n] = E;
}

__global__ __launch_bounds__(256) void scatter_kernel(const long long* __restrict__ ei,
                                                      int* __restrict__ cursor,
                                                      int* __restrict__ col, int E, int n) {
    int is64 = detect_is64(ei, E, n);
    int e = blockIdx.x * blockDim.x + threadIdx.x;
    if (e >= E) return;
    int src, dst;
    if (is64) { src = (int)ei[e]; dst = (int)ei[E + e]; }
    else { src = ((const int*)ei)[e]; dst = ((const int*)ei)[E + e]; }
    int pos = atomicAdd(&cursor[dst], 1);
    col[pos] = src;
}

// ---------------------------------------------------------------------------
// GEMM (h = x @ W, K=128) fused with attention dot products.
// 8x8 per thread.  FT=128: 128x128 tile; FT=64: 256x64 tile.  256 threads.
// xs stored row-major, row stride 36 floats (16B-aligned, conflict-free).
// Epilogue reduces acc over each head's 8 cq-lanes for a_s/a_d.
// ---------------------------------------------------------------------------
template <int FT>
__global__ __launch_bounds__(256) void gemm_att_kernel(
    const float* __restrict__ x, const float* __restrict__ W,
    const float* __restrict__ attS, const float* __restrict__ attD,
    float* __restrict__ h, float* __restrict__ as_, float* __restrict__ ad_,
    int n)
{
    constexpr int ROWS = (FT == 128) ? 128 : 256;
    constexpr int CQN  = FT / 8;            // 16 or 8
    constexpr int XSS  = 36;                // xs row stride (floats)
    __shared__ float xs[ROWS * XSS];
    __shared__ float Ws[32 * FT];

    const int tid = threadIdx.x;
    const int cq  = tid % CQN;
    const int rq  = tid / CQN;
    const int row0 = blockIdx.x * ROWS;

    float acc[8][8];
#pragma unroll
    for (int j = 0; j < 8; j++)
#pragma unroll
        for (int c = 0; c < 8; c++) acc[j][c] = 0.f;

    for (int kc = 0; kc < 128; kc += 32) {
        for (int t = tid; t < ROWS * 8; t += 256) {
            int r = t >> 3, kq = t & 7;
            float4 v = make_float4(0.f, 0.f, 0.f, 0.f);
            if (row0 + r < n)
                v = *(const float4*)&x[(long long)(row0 + r) * 128 + kc + kq * 4];
            *(float4*)&xs[r * XSS + kq * 4] = v;
        }
        for (int t = tid; t < 8 * FT; t += 256) {
            int kk = t / (FT / 4), c4 = t % (FT / 4);
            *(float4*)&Ws[kk * FT + c4 * 4] = *(const float4*)&W[(kc + kk) * FT + c4 * 4];
        }
        __syncthreads();
#pragma unroll 4
        for (int k = 0; k < 32; k++) {
            float4 wa = *(float4*)&Ws[k * FT + cq * 8];
            float4 wb = *(float4*)&Ws[k * FT + cq * 8 + 4];
            float xv[8];
#pragma unroll
            for (int j = 0; j < 8; j++) xv[j] = xs[(rq * 8 + j) * XSS + k];
#pragma unroll
            for (int j = 0; j < 8; j++) {
                acc[j][0] += xv[j] * wa.x;
                acc[j][1] += xv[j] * wa.y;
                acc[j][2] += xv[j] * wa.z;
                acc[j][3] += xv[j] * wa.w;
                acc[j][4] += xv[j] * wb.x;
                acc[j][5] += xv[j] * wb.y;
                acc[j][6] += xv[j] * wb.z;
                acc[j][7] += xv[j] * wb.w;
            }
        }
        __syncthreads();
    }

    // attention vectors for this thread's 8 columns
    float aS[8], aD[8];
    {
        float4 a0 = *(const float4*)&attS[cq * 8];
        float4 a1 = *(const float4*)&attS[cq * 8 + 4];
        aS[0]=a0.x; aS[1]=a0.y; aS[2]=a0.z; aS[3]=a0.w;
        aS[4]=a1.x; aS[5]=a1.y; aS[6]=a1.z; aS[7]=a1.w;
        float4 d0 = *(const float4*)&attD[cq * 8];
        float4 d1 = *(const float4*)&attD[cq * 8 + 4];
        aD[0]=d0.x; aD[1]=d0.y; aD[2]=d0.z; aD[3]=d0.w;
        aD[4]=d1.x; aD[5]=d1.y; aD[6]=d1.z; aD[7]=d1.w;
    }

#pragma unroll
    for (int j = 0; j < 8; j++) {
        int r = row0 + rq * 8 + j;
        float ps = 0.f, pd = 0.f;
#pragma unroll
        for (int c = 0; c < 8; c++) { ps += acc[j][c] * aS[c]; pd += acc[j][c] * aD[c]; }
#pragma unroll
        for (int o = 1; o < 8; o <<= 1) {
            ps += __shfl_xor_sync(0xffffffffu, ps, o);
            pd += __shfl_xor_sync(0xffffffffu, pd, o);
        }
        if (r < n) {
            if (FT == 128) {
                if ((cq & 7) == 0) {
                    as_[(long long)r * 2 + (cq >> 3)] = ps;
                    ad_[(long long)r * 2 + (cq >> 3)] = pd;
                }
            } else {
                if (cq == 0) { as_[r] = ps; ad_[r] = pd; }
            }
            float4 a = make_float4(acc[j][0], acc[j][1], acc[j][2], acc[j][3]);
            float4 b = make_float4(acc[j][4], acc[j][5], acc[j][6], acc[j][7]);
            *(float4*)&h[(long long)r * FT + cq * 8]     = a;
            *(float4*)&h[(long long)r * FT + cq * 8 + 4] = b;
        }
    }
}

__device__ __forceinline__ float leaky_exp(float a) {
    a = a > 0.f ? a : 0.2f * a;
    return __expf(a);
}

// ---------------------------------------------------------------------------
// Layer-1 aggregation (CSR): warp per node, F=128, 2 heads, unroll-4 gather.
// Fuses softmax normalize + bias + ELU; writes x2.
// ---------------------------------------------------------------------------
__global__ __launch_bounds__(256) void agg1_kernel(const int* __restrict__ rowptr,
                                                   const int* __restrict__ col,
                                                   const float* __restrict__ h,
                                                   const float* __restrict__ as_,
                                                   const float* __restrict__ ad_,
                                                   const float* __restrict__ b1,
                                                   float* __restrict__ o, int n) {
    int i    = (blockIdx.x * blockDim.x + threadIdx.x) >> 5;
    int lane = threadIdx.x & 31;
    if (i >= n) return;
    int head = lane >> 4;
    const float4* h4 = (const float4*)h;

    float adv = ad_[i * 2 + head];
    // self loop
    float w = leaky_exp(as_[i * 2 + head] + adv);
    float4 hv = h4[(long long)i * 32 + lane];
    float4 acc = make_float4(hv.x * w, hv.y * w, hv.z * w, hv.w * w);
    float den = w;

    int s0 = rowptr[i], s1 = rowptr[i + 1];
    int j = s0;
    for (; j + 3 < s1; j += 4) {
        int sA = col[j], sB = col[j + 1], sC = col[j + 2], sD = col[j + 3];
        float wA = leaky_exp(as_[sA * 2 + head] + adv);
        float wB = leaky_exp(as_[sB * 2 + head] + adv);
        float wC = leaky_exp(as_[sC * 2 + head] + adv);
        float wD = leaky_exp(as_[sD * 2 + head] + adv);
        float4 hA = h4[(long long)sA * 32 + lane];
        float4 hB = h4[(long long)sB * 32 + lane];
        float4 hC = h4[(long long)sC * 32 + lane];
        float4 hD = h4[(long long)sD * 32 + lane];
        acc.x += hA.x * wA + hB.x * wB + hC.x * wC + hD.x * wD;
        acc.y += hA.y * wA + hB.y * wB + hC.y * wC + hD.y * wD;
        acc.z += hA.z * wA + hB.z * wB + hC.z * wC + hD.z * wD;
        acc.w += hA.w * wA + hB.w * wB + hC.w * wC + hD.w * wD;
        den += wA + wB + wC + wD;
    }
    for (; j < s1; j++) {
        int s = col[j];
        w = leaky_exp(as_[s * 2 + head] + adv);
        hv = h4[(long long)s * 32 + lane];
        acc.x += hv.x * w; acc.y += hv.y * w; acc.z += hv.z * w; acc.w += hv.w * w;
        den += w;
    }
    float inv = 1.f / (den + 1e-16f);
    float4 bv = ((const float4*)b1)[lane];
    float4 v;
    v.x = acc.x * inv + bv.x;
    v.y = acc.y * inv + bv.y;
    v.z = acc.z * inv + bv.z;
    v.w = acc.w * inv + bv.w;
    v.x = v.x > 0.f ? v.x : expm1f(v.x);
    v.y = v.y > 0.f ? v.y : expm1f(v.y);
    v.z = v.z > 0.f ? v.z : expm1f(v.z);
    v.w = v.w > 0.f ? v.w : expm1f(v.w);
    ((float4*)o)[(long long)i * 32 + lane] = v;
}

// ---------------------------------------------------------------------------
// Layer-2 aggregation (CSR): warp per node, F=64, 1 head, 2 half-warps x
// unroll-2 (MLP 4).  Fuses normalize + bias + ELU; writes o2.
// ---------------------------------------------------------------------------
__global__ __launch_bounds__(256) void agg2_kernel(const int* __restrict__ rowptr,
                                                   const int* __restrict__ col,
                                                   const float* __restrict__ h,
                                                   const float* __restrict__ as_,
                                                   const float* __restrict__ ad_,
                                                   const float* __restrict__ b2,
                                                   float* __restrict__ o, int n) {
    int i    = (blockIdx.x * blockDim.x + threadIdx.x) >> 5;
    int lane = threadIdx.x & 31;
    if (i >= n) return;
    int sub = lane >> 4, ln = lane & 15;
    const float4* h4 = (const float4*)h;

    float adv = ad_[i];
    float4 acc = make_float4(0.f, 0.f, 0.f, 0.f);
    float den = 0.f;
    if (sub == 0) {  // self loop
        float w = leaky_exp(as_[i] + adv);
        float4 hv = h4[(long long)i * 16 + ln];
        acc = make_float4(hv.x * w, hv.y * w, hv.z * w, hv.w * w);
        den = w;
    }
    int s0 = rowptr[i], s1 = rowptr[i + 1];
    int j = s0 + sub;
    for (; j + 2 < s1; j += 4) {
        int sA = col[j], sB = col[j + 2];
        float wA = leaky_exp(as_[sA] + adv);
        float wB = leaky_exp(as_[sB] + adv);
        float4 hA = h4[(long long)sA * 16 + ln];
        float4 hB = h4[(long long)sB * 16 + ln];
        acc.x += hA.x * wA + hB.x * wB;
        acc.y += hA.y * wA + hB.y * wB;
        acc.z += hA.z * wA + hB.z * wB;
        acc.w += hA.w * wA + hB.w * wB;
        den += wA + wB;
    }
    for (; j < s1; j += 2) {
        int s = col[j];
        float w = leaky_exp(as_[s] + adv);
        float4 hv = h4[(long long)s * 16 + ln];
        acc.x += hv.x * w; acc.y += hv.y * w; acc.z += hv.z * w; acc.w += hv.w * w;
        den += w;
    }
    acc.x += __shfl_xor_sync(0xffffffffu, acc.x, 16);
    acc.y += __shfl_xor_sync(0xffffffffu, acc.y, 16);
    acc.z += __shfl_xor_sync(0xffffffffu, acc.z, 16);
    acc.w += __shfl_xor_sync(0xffffffffu, acc.w, 16);
    den   += __shfl_xor_sync(0xffffffffu, den, 16);
    if (sub == 0) {
        float inv = 1.f / (den + 1e-16f);
        float4 bv = ((const float4*)b2)[ln];
        float4 v;
        v.x = acc.x * inv + bv.x;
        v.y = acc.y * inv + bv.y;
        v.z = acc.z * inv + bv.z;
        v.w = acc.w * inv + bv.w;
        v.x = v.x > 0.f ? v.x : expm1f(v.x);
        v.y = v.y > 0.f ? v.y : expm1f(v.y);
        v.z = v.z > 0.f ? v.z : expm1f(v.z);
        v.w = v.w > 0.f ? v.w : expm1f(v.w);
        ((float4*)o)[(long long)i * 16 + ln] = v;
    }
}

// ---------------------------------------------------------------------------
// Final linear(64->16) + sigmoid.  16 nodes per block.
// ---------------------------------------------------------------------------
__global__ __launch_bounds__(256) void final_kernel(const float* __restrict__ o2,
                                                    const float* __restrict__ lw,
                                                    const float* __restrict__ lb,
                                                    float* __restrict__ out, int n) {
    __shared__ float lwsm[64 * 16];
    __shared__ float lbsm[16];
    __shared__ float o2sm[16 * 64];
    int tid = threadIdx.x;
    for (int i = tid; i < 1024; i += 256) lwsm[i] = lw[i];
    if (tid < 16) lbsm[tid] = lb[tid];

    int nb = blockIdx.x * 16;
    for (int t = tid; t < 16 * 64; t += 256) {
        int node = nb + (t >> 6);
        o2sm[t] = (node < n) ? o2[(long long)node * 64 + (t & 63)] : 0.f;
    }
    __syncthreads();

    int node = nb + (tid >> 4);
    int c = tid & 15;
    if (node < n) {
        float s = lbsm[c];
        const float* ov = &o2sm[(tid >> 4) << 6];
#pragma unroll
        for (int k = 0; k < 64; k++) s += ov[k] * lwsm[k * 16 + c];
        out[(long long)node * 16 + c] = 1.f / (1.f + __expf(-s));
    }
}

// ---------------------------------------------------------------------------
extern "C" void kernel_launch(void* const* d_in, const int* in_sizes, int n_in,
                              void* d_out, int out_size)
{
    const float*     x     = (const float*)d_in[0];
    const long long* ei    = (const long long*)d_in[1];
    const float*     W1    = (const float*)d_in[2];
    const float*     asrc1 = (const float*)d_in[3];
    const float*     adst1 = (const float*)d_in[4];
    const float*     b1    = (const float*)d_in[5];
    const float*     W2    = (const float*)d_in[6];
    const float*     asrc2 = (const float*)d_in[7];
    const float*     adst2 = (const float*)d_in[8];
    const float*     b2    = (const float*)d_in[9];
    const float*     lw    = (const float*)d_in[10];
    const float*     lb    = (const float*)d_in[11];

    int n = in_sizes[0] / 128;
    int E = in_sizes[1] / 2;

    float *h1, *as1, *ad1, *x2, *h2, *as2, *ad2, *o2;
    int *deg, *rowptr, *cursor, *col, *bsum, *boff;
    cudaGetSymbolAddress((void**)&h1,     g_h1);
    cudaGetSymbolAddress((void**)&as1,    g_as1);
    cudaGetSymbolAddress((void**)&ad1,    g_ad1);
    cudaGetSymbolAddress((void**)&x2,     g_x2);
    cudaGetSymbolAddress((void**)&h2,     g_h2);
    cudaGetSymbolAddress((void**)&as2,    g_as2);
    cudaGetSymbolAddress((void**)&ad2,    g_ad2);
    cudaGetSymbolAddress((void**)&o2,     g_o2);
    cudaGetSymbolAddress((void**)&deg,    g_deg);
    cudaGetSymbolAddress((void**)&rowptr, g_rowptr);
    cudaGetSymbolAddress((void**)&cursor, g_cursor);
    cudaGetSymbolAddress((void**)&col,    g_col);
    cudaGetSymbolAddress((void**)&bsum,   g_bsum);
    cudaGetSymbolAddress((void**)&boff,   g_boff);

    int nb = (n + SCAN_TILE - 1) / SCAN_TILE;

    // (0..2) CSR prologue
    zero_deg_kernel<<<(n + 255) / 256, 256>>>(deg, n);
    hist_kernel<<<(E + 255) / 256, 256>>>(ei, deg, E, n);
    scan1_kernel<<<nb, 256>>>(deg, bsum, n);
    // (3) layer-1 GEMM + attention dots  (target for ncu's profiled launch)
    gemm_att_kernel<128><<<(n + 127) / 128, 256>>>(x, W1, asrc1, adst1, h1, as1, ad1, n);
    // (4..6) CSR finish
    scan2_kernel<<<1, 64>>>(bsum, boff, nb);
    scan3_kernel<<<nb, 256>>>(deg, boff, rowptr, cursor, n, E);
    scatter_kernel<<<(E + 255) / 256, 256>>>(ei, cursor, col, E, n);
    // (7) layer-1 aggregation -> x2 (fused normalize/bias/elu)
    agg1_kernel<<<(n * 32 + 255) / 256, 256>>>(rowptr, col, h1, as1, ad1, b1, x2, n);
    // (8) layer-2 GEMM + attention dots
    gemm_att_kernel<64><<<(n + 255) / 256, 256>>>(x2, W2, asrc2, adst2, h2, as2, ad2, n);
    // (9) layer-2 aggregation -> o2
    agg2_kernel<<<(n * 32 + 255) / 256, 256>>>(rowptr, col, h2, as2, ad2, b2, o2, n);
    // (10) linear + sigmoid
    final_kernel<<<(n + 15) / 16, 256>>>(o2, lw, lb, (float*)d_out, n);
}

// round 4
// speedup vs baseline: 1.1355x; 1.1355x over previous
#include <cuda_runtime.h>
#include <math.h>

// ---------------------------------------------------------------------------
// GAT 2-layer forward, CSR aggregation, fused GEMM+attention-dots.
//   128 -> GAT(2x64, concat) -> elu -> GAT(1x64, mean) -> elu -> lin(64->16)
//   -> sigmoid.  Softmax max-shift skipped (logits O(+-6), shift-invariant).
// GEMM: x tile stored k-major in smem (vector LDS), double-buffered K chunks.
// ---------------------------------------------------------------------------

#define NMAX 50176
#define EMAX 1200000
#define SCAN_TILE 1024

__device__ float g_h1  [NMAX * 128];
__device__ float g_as1 [NMAX * 2];
__device__ float g_ad1 [NMAX * 2];
__device__ float g_x2  [NMAX * 128];
__device__ float g_h2  [NMAX * 64];
__device__ float g_as2 [NMAX];
__device__ float g_ad2 [NMAX];
__device__ float g_o2  [NMAX * 64];
__device__ int   g_deg [NMAX];
__device__ int   g_rowptr[NMAX + 1];
__device__ int   g_cursor[NMAX];
__device__ int   g_col [EMAX];
__device__ int   g_bsum[256];
__device__ int   g_boff[256];

// ---------------------------------------------------------------------------
// Per-block int64-vs-int32 edge width detection (first 1024 entries, L2-hot).
// ---------------------------------------------------------------------------
__device__ __forceinline__ int detect_is64(const long long* __restrict__ ei,
                                           int E, int n) {
    int cnt = E < 1024 ? E : 1024;
    int local = 0;
    for (int i = threadIdx.x; i < cnt; i += blockDim.x) {
        long long v = __ldg(&ei[i]);
        if (v < 0 || v >= (long long)n) local = 1;
    }
    if (__syncthreads_or(local)) return 0;
    return 1;
}

__global__ void zero_deg_kernel(int* __restrict__ deg, int n) {
    int i = blockIdx.x * blockDim.x + threadIdx.x;
    if (i < n) deg[i] = 0;
}

__global__ __launch_bounds__(256) void hist_kernel(const long long* __restrict__ ei,
                                                   int* __restrict__ deg, int E, int n) {
    int is64 = detect_is64(ei, E, n);
    int e = blockIdx.x * blockDim.x + threadIdx.x;
    if (e >= E) return;
    int dst = is64 ? (int)ei[E + e] : ((const int*)ei)[E + e];
    atomicAdd(&deg[dst], 1);
}

// ---------------------------------------------------------------------------
// 3-step exclusive scan of deg -> rowptr (+ cursor copy).
// ---------------------------------------------------------------------------
__global__ __launch_bounds__(256) void scan1_kernel(const int* __restrict__ deg,
                                                    int* __restrict__ bsum, int n) {
    __shared__ int sm[256];
    int base = blockIdx.x * SCAN_TILE;
    int s = 0;
    for (int i = base + threadIdx.x; i < base + SCAN_TILE && i < n; i += 256) s += deg[i];
    sm[threadIdx.x] = s;
    __syncthreads();
    for (int off = 128; off; off >>= 1) {
        if (threadIdx.x < off) sm[threadIdx.x] += sm[threadIdx.x + off];
        __syncthreads();
    }
    if (threadIdx.x == 0) bsum[blockIdx.x] = sm[0];
}

__global__ void scan2_kernel(const int* __restrict__ bsum, int* __restrict__ boff, int nb) {
    __shared__ int sm[64];
    int t = threadIdx.x;
    sm[t] = (t < nb) ? bsum[t] : 0;
    __syncthreads();
    for (int off = 1; off < 64; off <<= 1) {
        int v = (t >= off) ? sm[t - off] : 0;
        __syncthreads();
        sm[t] += v;
        __syncthreads();
    }
    if (t < nb) boff[t] = sm[t] - bsum[t];   // exclusive
}

__global__ __launch_bounds__(256) void scan3_kernel(const int* __restrict__ deg,
                                                    const int* __restrict__ boff,
                                                    int* __restrict__ rowptr,
                                                    int* __restrict__ cursor,
                                                    int n, int E) {
    __shared__ int sm[256];
    int base = blockIdx.x * SCAN_TILE;
    int tid = threadIdx.x;
    int v[4];
    int tsum = 0;
#pragma unroll
    for (int m = 0; m < 4; m++) {
        int i = base + tid * 4 + m;
        v[m] = (i < n) ? deg[i] : 0;
        tsum += v[m];
    }
    sm[tid] = tsum;
    __syncthreads();
    int run = tsum;
    for (int off = 1; off < 256; off <<= 1) {
        int t = (tid >= off) ? sm[tid - off] : 0;
        __syncthreads();
        sm[tid] += t;
        __syncthreads();
    }
    int excl = sm[tid] - run + boff[blockIdx.x];
#pragma unroll
    for (int m = 0; m < 4; m++) {
        int i = base + tid * 4 + m;
        if (i < n) { rowptr[i] = excl; cursor[i] = excl; }
        excl += v[m];
    }
    if (blockIdx.x == 0 && tid == 0) rowptr[n] = E;
}

__global__ __launch_bounds__(256) void scatter_kernel(const long long* __restrict__ ei,
                                                      int* __restrict__ cursor,
                                                      int* __restrict__ col, int E, int n) {
    int is64 = detect_is64(ei, E, n);
    int e = blockIdx.x * blockDim.x + threadIdx.x;
    if (e >= E) return;
    int src, dst;
    if (is64) { src = (int)ei[e]; dst = (int)ei[E + e]; }
    else { src = ((const int*)ei)[e]; dst = ((const int*)ei)[E + e]; }
    int pos = atomicAdd(&cursor[dst], 1);
    col[pos] = src;
}

// ---------------------------------------------------------------------------
// GEMM (h = x @ W, K=128) fused with attention dot products.
// Block tile 128 rows x FT cols, 256 threads.
//   FT=128: thread tile 8x8 (cq = tid%16, rq = tid/16)
//   FT=64 : thread tile 4x8 (cq = tid%8,  rq = tid/8)
// x tile stored k-major (xsT[k][r], pad 132) so row reads are LDS.128.
// Double-buffered K chunks of 16; LDG for chunk c+1 issued before compute c.
// ---------------------------------------------------------------------------
template <int FT>
__global__ __launch_bounds__(256, 2) void gemm_att_kernel(
    const float* __restrict__ x, const float* __restrict__ W,
    const float* __restrict__ attS, const float* __restrict__ attD,
    float* __restrict__ h, float* __restrict__ as_, float* __restrict__ ad_,
    int n)
{
    constexpr int CQN  = FT / 8;               // 16 or 8
    constexpr int RPT  = (FT == 128) ? 8 : 4;  // rows per thread
    constexpr int RPAD = 132;
    constexpr int KC   = 16;
    constexpr int NW   = KC * FT;              // W chunk floats
    constexpr int WPT  = NW / 4 / 256;         // W float4s per thread (2 or 1)
    __shared__ float xsT[2 * KC * RPAD];
    __shared__ float Wss[2 * NW];

    const int tid  = threadIdx.x;
    const int cq   = tid % CQN;
    const int rq   = tid / CQN;
    const int row0 = blockIdx.x * 128;

    float acc[RPT][8];
#pragma unroll
    for (int j = 0; j < RPT; j++)
#pragma unroll
        for (int c = 0; c < 8; c++) acc[j][c] = 0.f;

    float4 xst[2];
    float4 wst[WPT];

    auto ldg = [&](int kc) {
#pragma unroll
        for (int i = 0; i < 2; i++) {
            int t = tid + i * 256;
            int r = t >> 2, kq4 = t & 3;
            float4 v = make_float4(0.f, 0.f, 0.f, 0.f);
            if (row0 + r < n)
                v = *(const float4*)&x[(long long)(row0 + r) * 128 + kc + kq4 * 4];
            xst[i] = v;
        }
#pragma unroll
        for (int i = 0; i < WPT; i++) {
            int t = tid + i * 256;
            int kk = t / (FT / 4), c4 = t % (FT / 4);
            wst[i] = *(const float4*)&W[(long long)(kc + kk) * FT + c4 * 4];
        }
    };
    auto sts = [&](int buf) {
        float* xd = &xsT[buf * KC * RPAD];
        float* wd = &Wss[buf * NW];
#pragma unroll
        for (int i = 0; i < 2; i++) {
            int t = tid + i * 256;
            int r = t >> 2, kq4 = t & 3;
            xd[(kq4 * 4 + 0) * RPAD + r] = xst[i].x;
            xd[(kq4 * 4 + 1) * RPAD + r] = xst[i].y;
            xd[(kq4 * 4 + 2) * RPAD + r] = xst[i].z;
            xd[(kq4 * 4 + 3) * RPAD + r] = xst[i].w;
        }
#pragma unroll
        for (int i = 0; i < WPT; i++) {
            int t = tid + i * 256;
            int kk = t / (FT / 4), c4 = t % (FT / 4);
            *(float4*)&wd[kk * FT + c4 * 4] = wst[i];
        }
    };

    ldg(0);
    sts(0);
    __syncthreads();

    for (int c = 0; c < 8; c++) {
        if (c < 7) ldg((c + 1) * KC);
        const float* xb = &xsT[(c & 1) * KC * RPAD];
        const float* wb = &Wss[(c & 1) * NW];
#pragma unroll 4
        for (int k = 0; k < KC; k++) {
            float4 wa = *(const float4*)&wb[k * FT + cq * 8];
            float4 wc = *(const float4*)&wb[k * FT + cq * 8 + 4];
            float xv[RPT];
            if (RPT == 8) {
                float4 x0 = *(const float4*)&xb[k * RPAD + rq * 8];
                float4 x1 = *(const float4*)&xb[k * RPAD + rq * 8 + 4];
                xv[0] = x0.x; xv[1] = x0.y; xv[2] = x0.z; xv[3] = x0.w;
                xv[4] = x1.x; xv[5] = x1.y; xv[6] = x1.z; xv[7] = x1.w;
            } else {
                float4 x0 = *(const float4*)&xb[k * RPAD + rq * 4];
                xv[0] = x0.x; xv[1] = x0.y; xv[2] = x0.z; xv[3] = x0.w;
            }
#pragma unroll
            for (int j = 0; j < RPT; j++) {
                acc[j][0] += xv[j] * wa.x;
                acc[j][1] += xv[j] * wa.y;
                acc[j][2] += xv[j] * wa.z;
                acc[j][3] += xv[j] * wa.w;
                acc[j][4] += xv[j] * wc.x;
                acc[j][5] += xv[j] * wc.y;
                acc[j][6] += xv[j] * wc.z;
                acc[j][7] += xv[j] * wc.w;
            }
        }
        if (c < 7) sts((c + 1) & 1);
        __syncthreads();
    }

    // attention vectors for this thread's 8 columns
    float aS[8], aD[8];
    {
        float4 a0 = *(const float4*)&attS[cq * 8];
        float4 a1 = *(const float4*)&attS[cq * 8 + 4];
        aS[0]=a0.x; aS[1]=a0.y; aS[2]=a0.z; aS[3]=a0.w;
        aS[4]=a1.x; aS[5]=a1.y; aS[6]=a1.z; aS[7]=a1.w;
        float4 d0 = *(const float4*)&attD[cq * 8];
        float4 d1 = *(const float4*)&attD[cq * 8 + 4];
        aD[0]=d0.x; aD[1]=d0.y; aD[2]=d0.z; aD[3]=d0.w;
        aD[4]=d1.x; aD[5]=d1.y; aD[6]=d1.z; aD[7]=d1.w;
    }

#pragma unroll
    for (int j = 0; j < RPT; j++) {
        int r = row0 + rq * RPT + j;
        float ps = 0.f, pd = 0.f;
#pragma unroll
        for (int c = 0; c < 8; c++) { ps += acc[j][c] * aS[c]; pd += acc[j][c] * aD[c]; }
#pragma unroll
        for (int o = 1; o < 8; o <<= 1) {
            ps += __shfl_xor_sync(0xffffffffu, ps, o);
            pd += __shfl_xor_sync(0xffffffffu, pd, o);
        }
        if (r < n) {
            if (FT == 128) {
                if ((cq & 7) == 0) {
                    as_[(long long)r * 2 + (cq >> 3)] = ps;
                    ad_[(long long)r * 2 + (cq >> 3)] = pd;
                }
            } else {
                if (cq == 0) { as_[r] = ps; ad_[r] = pd; }
            }
            float4 a = make_float4(acc[j][0], acc[j][1], acc[j][2], acc[j][3]);
            float4 b = make_float4(acc[j][4], acc[j][5], acc[j][6], acc[j][7]);
            *(float4*)&h[(long long)r * FT + cq * 8]     = a;
            *(float4*)&h[(long long)r * FT + cq * 8 + 4] = b;
        }
    }
}

__device__ __forceinline__ float leaky_exp(float a) {
    a = a > 0.f ? a : 0.2f * a;
    return __expf(a);
}

// ---------------------------------------------------------------------------
// Layer-1 aggregation (CSR): warp per node, F=128, 2 heads, unroll-4 gather.
// Fuses softmax normalize + bias + ELU; writes x2.
// ---------------------------------------------------------------------------
__global__ __launch_bounds__(256) void agg1_kernel(const int* __restrict__ rowptr,
                                                   const int* __restrict__ col,
                                                   const float* __restrict__ h,
                                                   const float* __restrict__ as_,
                                                   const float* __restrict__ ad_,
                                                   const float* __restrict__ b1,
                                                   float* __restrict__ o, int n) {
    int i    = (blockIdx.x * blockDim.x + threadIdx.x) >> 5;
    int lane = threadIdx.x & 31;
    if (i >= n) return;
    int head = lane >> 4;
    const float4* h4 = (const float4*)h;

    float adv = ad_[i * 2 + head];
    // self loop
    float w = leaky_exp(as_[i * 2 + head] + adv);
    float4 hv = h4[(long long)i * 32 + lane];
    float4 acc = make_float4(hv.x * w, hv.y * w, hv.z * w, hv.w * w);
    float den = w;

    int s0 = rowptr[i], s1 = rowptr[i + 1];
    int j = s0;
    for (; j + 3 < s1; j += 4) {
        int sA = col[j], sB = col[j + 1], sC = col[j + 2], sD = col[j + 3];
        float wA = leaky_exp(as_[sA * 2 + head] + adv);
        float wB = leaky_exp(as_[sB * 2 + head] + adv);
        float wC = leaky_exp(as_[sC * 2 + head] + adv);
        float wD = leaky_exp(as_[sD * 2 + head] + adv);
        float4 hA = h4[(long long)sA * 32 + lane];
        float4 hB = h4[(long long)sB * 32 + lane];
        float4 hC = h4[(long long)sC * 32 + lane];
        float4 hD = h4[(long long)sD * 32 + lane];
        acc.x += hA.x * wA + hB.x * wB + hC.x * wC + hD.x * wD;
        acc.y += hA.y * wA + hB.y * wB + hC.y * wC + hD.y * wD;
        acc.z += hA.z * wA + hB.z * wB + hC.z * wC + hD.z * wD;
        acc.w += hA.w * wA + hB.w * wB + hC.w * wC + hD.w * wD;
        den += wA + wB + wC + wD;
    }
    for (; j < s1; j++) {
        int s = col[j];
        w = leaky_exp(as_[s * 2 + head] + adv);
        hv = h4[(long long)s * 32 + lane];
        acc.x += hv.x * w; acc.y += hv.y * w; acc.z += hv.z * w; acc.w += hv.w * w;
        den += w;
    }
    float inv = 1.f / (den + 1e-16f);
    float4 bv = ((const float4*)b1)[lane];
    float4 v;
    v.x = acc.x * inv + bv.x;
    v.y = acc.y * inv + bv.y;
    v.z = acc.z * inv + bv.z;
    v.w = acc.w * inv + bv.w;
    v.x = v.x > 0.f ? v.x : expm1f(v.x);
    v.y = v.y > 0.f ? v.y : expm1f(v.y);
    v.z = v.z > 0.f ? v.z : expm1f(v.z);
    v.w = v.w > 0.f ? v.w : expm1f(v.w);
    ((float4*)o)[(long long)i * 32 + lane] = v;
}

// ---------------------------------------------------------------------------
// Layer-2 aggregation (CSR): warp per node, F=64, 1 head, 2 half-warps x
// unroll-2 (MLP 4).  Fuses normalize + bias + ELU; writes o2.
// ---------------------------------------------------------------------------
__global__ __launch_bounds__(256) void agg2_kernel(const int* __restrict__ rowptr,
                                                   const int* __restrict__ col,
                                                   const float* __restrict__ h,
                                                   const float* __restrict__ as_,
                                                   const float* __restrict__ ad_,
                                                   const float* __restrict__ b2,
                                                   float* __restrict__ o, int n) {
    int i    = (blockIdx.x * blockDim.x + threadIdx.x) >> 5;
    int lane = threadIdx.x & 31;
    if (i >= n) return;
    int sub = lane >> 4, ln = lane & 15;
    const float4* h4 = (const float4*)h;

    float adv = ad_[i];
    float4 acc = make_float4(0.f, 0.f, 0.f, 0.f);
    float den = 0.f;
    if (sub == 0) {  // self loop
        float w = leaky_exp(as_[i] + adv);
        float4 hv = h4[(long long)i * 16 + ln];
        acc = make_float4(hv.x * w, hv.y * w, hv.z * w, hv.w * w);
        den = w;
    }
    int s0 = rowptr[i], s1 = rowptr[i + 1];
    int j = s0 + sub;
    for (; j + 2 < s1; j += 4) {
        int sA = col[j], sB = col[j + 2];
        float wA = leaky_exp(as_[sA] + adv);
        float wB = leaky_exp(as_[sB] + adv);
        float4 hA = h4[(long long)sA * 16 + ln];
        float4 hB = h4[(long long)sB * 16 + ln];
        acc.x += hA.x * wA + hB.x * wB;
        acc.y += hA.y * wA + hB.y * wB;
        acc.z += hA.z * wA + hB.z * wB;
        acc.w += hA.w * wA + hB.w * wB;
        den += wA + wB;
    }
    for (; j < s1; j += 2) {
        int s = col[j];
        float w = leaky_exp(as_[s] + adv);
        float4 hv = h4[(long long)s * 16 + ln];
        acc.x += hv.x * w; acc.y += hv.y * w; acc.z += hv.z * w; acc.w += hv.w * w;
        den += w;
    }
    acc.x += __shfl_xor_sync(0xffffffffu, acc.x, 16);
    acc.y += __shfl_xor_sync(0xffffffffu, acc.y, 16);
    acc.z += __shfl_xor_sync(0xffffffffu, acc.z, 16);
    acc.w += __shfl_xor_sync(0xffffffffu, acc.w, 16);
    den   += __shfl_xor_sync(0xffffffffu, den, 16);
    if (sub == 0) {
        float inv = 1.f / (den + 1e-16f);
        float4 bv = ((const float4*)b2)[ln];
        float4 v;
        v.x = acc.x * inv + bv.x;
        v.y = acc.y * inv + bv.y;
        v.z = acc.z * inv + bv.z;
        v.w = acc.w * inv + bv.w;
        v.x = v.x > 0.f ? v.x : expm1f(v.x);
        v.y = v.y > 0.f ? v.y : expm1f(v.y);
        v.z = v.z > 0.f ? v.z : expm1f(v.z);
        v.w = v.w > 0.f ? v.w : expm1f(v.w);
        ((float4*)o)[(long long)i * 16 + ln] = v;
    }
}

// ---------------------------------------------------------------------------
// Final linear(64->16) + sigmoid.  16 nodes per block.
// ---------------------------------------------------------------------------
__global__ __launch_bounds__(256) void final_kernel(const float* __restrict__ o2,
                                                    const float* __restrict__ lw,
                                                    const float* __restrict__ lb,
                                                    float* __restrict__ out, int n) {
    __shared__ float lwsm[64 * 16];
    __shared__ float lbsm[16];
    __shared__ float o2sm[16 * 64];
    int tid = threadIdx.x;
    for (int i = tid; i < 1024; i += 256) lwsm[i] = lw[i];
    if (tid < 16) lbsm[tid] = lb[tid];

    int nb = blockIdx.x * 16;
    for (int t = tid; t < 16 * 64; t += 256) {
        int node = nb + (t >> 6);
        o2sm[t] = (node < n) ? o2[(long long)node * 64 + (t & 63)] : 0.f;
    }
    __syncthreads();

    int node = nb + (tid >> 4);
    int c = tid & 15;
    if (node < n) {
        float s = lbsm[c];
        const float* ov = &o2sm[(tid >> 4) << 6];
#pragma unroll
        for (int k = 0; k < 64; k++) s += ov[k] * lwsm[k * 16 + c];
        out[(long long)node * 16 + c] = 1.f / (1.f + __expf(-s));
    }
}

// ---------------------------------------------------------------------------
extern "C" void kernel_launch(void* const* d_in, const int* in_sizes, int n_in,
                              void* d_out, int out_size)
{
    const float*     x     = (const float*)d_in[0];
    const long long* ei    = (const long long*)d_in[1];
    const float*     W1    = (const float*)d_in[2];
    const float*     asrc1 = (const float*)d_in[3];
    const float*     adst1 = (const float*)d_in[4];
    const float*     b1    = (const float*)d_in[5];
    const float*     W2    = (const float*)d_in[6];
    const float*     asrc2 = (const float*)d_in[7];
    const float*     adst2 = (const float*)d_in[8];
    const float*     b2    = (const float*)d_in[9];
    const float*     lw    = (const float*)d_in[10];
    const float*     lb    = (const float*)d_in[11];

    int n = in_sizes[0] / 128;
    int E = in_sizes[1] / 2;

    float *h1, *as1, *ad1, *x2, *h2, *as2, *ad2, *o2;
    int *deg, *rowptr, *cursor, *col, *bsum, *boff;
    cudaGetSymbolAddress((void**)&h1,     g_h1);
    cudaGetSymbolAddress((void**)&as1,    g_as1);
    cudaGetSymbolAddress((void**)&ad1,    g_ad1);
    cudaGetSymbolAddress((void**)&x2,     g_x2);
    cudaGetSymbolAddress((void**)&h2,     g_h2);
    cudaGetSymbolAddress((void**)&as2,    g_as2);
    cudaGetSymbolAddress((void**)&ad2,    g_ad2);
    cudaGetSymbolAddress((void**)&o2,     g_o2);
    cudaGetSymbolAddress((void**)&deg,    g_deg);
    cudaGetSymbolAddress((void**)&rowptr, g_rowptr);
    cudaGetSymbolAddress((void**)&cursor, g_cursor);
    cudaGetSymbolAddress((void**)&col,    g_col);
    cudaGetSymbolAddress((void**)&bsum,   g_bsum);
    cudaGetSymbolAddress((void**)&boff,   g_boff);

    int nb = (n + SCAN_TILE - 1) / SCAN_TILE;

    // (0..2) CSR prologue
    zero_deg_kernel<<<(n + 255) / 256, 256>>>(deg, n);
    hist_kernel<<<(E + 255) / 256, 256>>>(ei, deg, E, n);
    scan1_kernel<<<nb, 256>>>(deg, bsum, n);
    // (3) layer-1 GEMM + attention dots  (ncu's profiled launch)
    gemm_att_kernel<128><<<(n + 127) / 128, 256>>>(x, W1, asrc1, adst1, h1, as1, ad1, n);
    // (4..6) CSR finish
    scan2_kernel<<<1, 64>>>(bsum, boff, nb);
    scan3_kernel<<<nb, 256>>>(deg, boff, rowptr, cursor, n, E);
    scatter_kernel<<<(E + 255) / 256, 256>>>(ei, cursor, col, E, n);
    // (7) layer-1 aggregation -> x2 (fused normalize/bias/elu)
    agg1_kernel<<<(n * 32 + 255) / 256, 256>>>(rowptr, col, h1, as1, ad1, b1, x2, n);
    // (8) layer-2 GEMM + attention dots
    gemm_att_kernel<64><<<(n + 127) / 128, 256>>>(x2, W2, asrc2, adst2, h2, as2, ad2, n);
    // (9) layer-2 aggregation -> o2
    agg2_kernel<<<(n * 32 + 255) / 256, 256>>>(rowptr, col, h2, as2, ad2, b2, o2, n);
    // (10) linear + sigmoid
    final_kernel<<<(n + 15) / 16, 256>>>(o2, lw, lb, (float*)d_out, n);
}

// round 5
// speedup vs baseline: 1.3640x; 1.2012x over previous
#include <cuda_runtime.h>
#include <cuda_fp16.h>
#include <math.h>

// ---------------------------------------------------------------------------
// GAT 2-layer forward, CSR aggregation, fused GEMM+attention-dots.
// h tables stored fp16 (halves L2 gather traffic in aggregation).
// CSR build overlapped with layer-1 GEMM via stream fork-join.
// ---------------------------------------------------------------------------

#define NMAX 50176
#define EMAX 1200000
#define SCAN_TILE 1024

__device__ __half g_h1 [NMAX * 128];
__device__ float  g_as1[NMAX * 2];
__device__ float  g_ad1[NMAX * 2];
__device__ float  g_x2 [NMAX * 128];
__device__ __half g_h2 [NMAX * 64];
__device__ float  g_as2[NMAX];
__device__ float  g_ad2[NMAX];
__device__ float  g_o2 [NMAX * 64];
__device__ int    g_deg[NMAX];
__device__ int    g_rowptr[NMAX + 1];
__device__ int    g_cursor[NMAX];
__device__ int    g_col[EMAX];
__device__ int    g_bsum[256];
__device__ int    g_boff[256];
__device__ int    g_is64;

// ---------------------------------------------------------------------------
// Zero deg; block 0 also detects edge-index width (int64 vs int32) once.
// ---------------------------------------------------------------------------
__global__ __launch_bounds__(256) void zero_deg_kernel(int* __restrict__ deg, int n,
                                                       const long long* __restrict__ ei,
                                                       int E) {
    int i = blockIdx.x * blockDim.x + threadIdx.x;
    if (i < n) deg[i] = 0;
    if (blockIdx.x == 0) {
        int cnt = E < 1024 ? E : 1024;
        int local = 0;
        for (int t = threadIdx.x; t < cnt; t += 256) {
            long long v = __ldg(&ei[t]);
            if (v < 0 || v >= (long long)n) local = 1;
        }
        int bad = __syncthreads_or(local);
        if (threadIdx.x == 0) g_is64 = bad ? 0 : 1;
    }
}

__global__ __launch_bounds__(256) void hist_kernel(const long long* __restrict__ ei,
                                                   int* __restrict__ deg, int E) {
    int is64 = g_is64;
    int e = blockIdx.x * blockDim.x + threadIdx.x;
    if (e >= E) return;
    int dst = is64 ? (int)ei[E + e] : ((const int*)ei)[E + e];
    atomicAdd(&deg[dst], 1);
}

// ---------------------------------------------------------------------------
// 3-step exclusive scan of deg -> rowptr (+ cursor copy).
// ---------------------------------------------------------------------------
__global__ __launch_bounds__(256) void scan1_kernel(const int* __restrict__ deg,
                                                    int* __restrict__ bsum, int n) {
    __shared__ int sm[256];
    int base = blockIdx.x * SCAN_TILE;
    int s = 0;
    for (int i = base + threadIdx.x; i < base + SCAN_TILE && i < n; i += 256) s += deg[i];
    sm[threadIdx.x] = s;
    __syncthreads();
    for (int off = 128; off; off >>= 1) {
        if (threadIdx.x < off) sm[threadIdx.x] += sm[threadIdx.x + off];
        __syncthreads();
    }
    if (threadIdx.x == 0) bsum[blockIdx.x] = sm[0];
}

__global__ void scan2_kernel(const int* __restrict__ bsum, int* __restrict__ boff, int nb) {
    __shared__ int sm[64];
    int t = threadIdx.x;
    sm[t] = (t < nb) ? bsum[t] : 0;
    __syncthreads();
    for (int off = 1; off < 64; off <<= 1) {
        int v = (t >= off) ? sm[t - off] : 0;
        __syncthreads();
        sm[t] += v;
        __syncthreads();
    }
    if (t < nb) boff[t] = sm[t] - bsum[t];   // exclusive
}

__global__ __launch_bounds__(256) void scan3_kernel(const int* __restrict__ deg,
                                                    const int* __restrict__ boff,
                                                    int* __restrict__ rowptr,
                                                    int* __restrict__ cursor,
                                                    int n, int E) {
    __shared__ int sm[256];
    int base = blockIdx.x * SCAN_TILE;
    int tid = threadIdx.x;
    int v[4];
    int tsum = 0;
#pragma unroll
    for (int m = 0; m < 4; m++) {
        int i = base + tid * 4 + m;
        v[m] = (i < n) ? deg[i] : 0;
        tsum += v[m];
    }
    sm[tid] = tsum;
    __syncthreads();
    int run = tsum;
    for (int off = 1; off < 256; off <<= 1) {
        int t = (tid >= off) ? sm[tid - off] : 0;
        __syncthreads();
        sm[tid] += t;
        __syncthreads();
    }
    int excl = sm[tid] - run + boff[blockIdx.x];
#pragma unroll
    for (int m = 0; m < 4; m++) {
        int i = base + tid * 4 + m;
        if (i < n) { rowptr[i] = excl; cursor[i] = excl; }
        excl += v[m];
    }
    if (blockIdx.x == 0 && tid == 0) rowptr[n] = E;
}

__global__ __launch_bounds__(256) void scatter_kernel(const long long* __restrict__ ei,
                                                      int* __restrict__ cursor,
                                                      int* __restrict__ col, int E) {
    int is64 = g_is64;
    int e = blockIdx.x * blockDim.x + threadIdx.x;
    if (e >= E) return;
    int src, dst;
    if (is64) { src = (int)ei[e]; dst = (int)ei[E + e]; }
    else { src = ((const int*)ei)[e]; dst = ((const int*)ei)[E + e]; }
    int pos = atomicAdd(&cursor[dst], 1);
    col[pos] = src;
}

// ---------------------------------------------------------------------------
// GEMM (h = x @ W, K=128) fused with attention dot products; h stored fp16.
// Block tile 128 rows x FT cols, 256 threads.
//   FT=128: thread tile 8x8;  FT=64: thread tile 4x8.
// x tile k-major in smem (vector LDS), double-buffered K chunks of 16.
// ---------------------------------------------------------------------------
template <int FT>
__global__ __launch_bounds__(256, 2) void gemm_att_kernel(
    const float* __restrict__ x, const float* __restrict__ W,
    const float* __restrict__ attS, const float* __restrict__ attD,
    __half* __restrict__ h, float* __restrict__ as_, float* __restrict__ ad_,
    int n)
{
    constexpr int CQN  = FT / 8;               // 16 or 8
    constexpr int RPT  = (FT == 128) ? 8 : 4;  // rows per thread
    constexpr int RPAD = 132;
    constexpr int KC   = 16;
    constexpr int NW   = KC * FT;
    constexpr int WPT  = NW / 4 / 256;
    __shared__ float xsT[2 * KC * RPAD];
    __shared__ float Wss[2 * NW];

    const int tid  = threadIdx.x;
    const int cq   = tid % CQN;
    const int rq   = tid / CQN;
    const int row0 = blockIdx.x * 128;

    float acc[RPT][8];
#pragma unroll
    for (int j = 0; j < RPT; j++)
#pragma unroll
        for (int c = 0; c < 8; c++) acc[j][c] = 0.f;

    float4 xst[2];
    float4 wst[WPT];

    auto ldg = [&](int kc) {
#pragma unroll
        for (int i = 0; i < 2; i++) {
            int t = tid + i * 256;
            int r = t >> 2, kq4 = t & 3;
            float4 v = make_float4(0.f, 0.f, 0.f, 0.f);
            if (row0 + r < n)
                v = *(const float4*)&x[(long long)(row0 + r) * 128 + kc + kq4 * 4];
            xst[i] = v;
        }
#pragma unroll
        for (int i = 0; i < WPT; i++) {
            int t = tid + i * 256;
            int kk = t / (FT / 4), c4 = t % (FT / 4);
            wst[i] = *(const float4*)&W[(long long)(kc + kk) * FT + c4 * 4];
        }
    };
    auto sts = [&](int buf) {
        float* xd = &xsT[buf * KC * RPAD];
        float* wd = &Wss[buf * NW];
#pragma unroll
        for (int i = 0; i < 2; i++) {
            int t = tid + i * 256;
            int r = t >> 2, kq4 = t & 3;
            xd[(kq4 * 4 + 0) * RPAD + r] = xst[i].x;
            xd[(kq4 * 4 + 1) * RPAD + r] = xst[i].y;
            xd[(kq4 * 4 + 2) * RPAD + r] = xst[i].z;
            xd[(kq4 * 4 + 3) * RPAD + r] = xst[i].w;
        }
#pragma unroll
        for (int i = 0; i < WPT; i++) {
            int t = tid + i * 256;
            int kk = t / (FT / 4), c4 = t % (FT / 4);
            *(float4*)&wd[kk * FT + c4 * 4] = wst[i];
        }
    };

    ldg(0);
    sts(0);
    __syncthreads();

    for (int c = 0; c < 8; c++) {
        if (c < 7) ldg((c + 1) * KC);
        const float* xb = &xsT[(c & 1) * KC * RPAD];
        const float* wb = &Wss[(c & 1) * NW];
#pragma unroll 8
        for (int k = 0; k < KC; k++) {
            float4 wa = *(const float4*)&wb[k * FT + cq * 8];
            float4 wc = *(const float4*)&wb[k * FT + cq * 8 + 4];
            float xv[RPT];
            if (RPT == 8) {
                float4 x0 = *(const float4*)&xb[k * RPAD + rq * 8];
                float4 x1 = *(const float4*)&xb[k * RPAD + rq * 8 + 4];
                xv[0] = x0.x; xv[1] = x0.y; xv[2] = x0.z; xv[3] = x0.w;
                xv[4] = x1.x; xv[5] = x1.y; xv[6] = x1.z; xv[7] = x1.w;
            } else {
                float4 x0 = *(const float4*)&xb[k * RPAD + rq * 4];
                xv[0] = x0.x; xv[1] = x0.y; xv[2] = x0.z; xv[3] = x0.w;
            }
#pragma unroll
            for (int j = 0; j < RPT; j++) {
                acc[j][0] += xv[j] * wa.x;
                acc[j][1] += xv[j] * wa.y;
                acc[j][2] += xv[j] * wa.z;
                acc[j][3] += xv[j] * wa.w;
                acc[j][4] += xv[j] * wc.x;
                acc[j][5] += xv[j] * wc.y;
                acc[j][6] += xv[j] * wc.z;
                acc[j][7] += xv[j] * wc.w;
            }
        }
        if (c < 7) sts((c + 1) & 1);
        __syncthreads();
    }

    // attention vectors for this thread's 8 columns
    float aS[8], aD[8];
    {
        float4 a0 = *(const float4*)&attS[cq * 8];
        float4 a1 = *(const float4*)&attS[cq * 8 + 4];
        aS[0]=a0.x; aS[1]=a0.y; aS[2]=a0.z; aS[3]=a0.w;
        aS[4]=a1.x; aS[5]=a1.y; aS[6]=a1.z; aS[7]=a1.w;
        float4 d0 = *(const float4*)&attD[cq * 8];
        float4 d1 = *(const float4*)&attD[cq * 8 + 4];
        aD[0]=d0.x; aD[1]=d0.y; aD[2]=d0.z; aD[3]=d0.w;
        aD[4]=d1.x; aD[5]=d1.y; aD[6]=d1.z; aD[7]=d1.w;
    }

#pragma unroll
    for (int j = 0; j < RPT; j++) {
        int r = row0 + rq * RPT + j;
        float ps = 0.f, pd = 0.f;
#pragma unroll
        for (int c = 0; c < 8; c++) { ps += acc[j][c] * aS[c]; pd += acc[j][c] * aD[c]; }
#pragma unroll
        for (int o = 1; o < 8; o <<= 1) {
            ps += __shfl_xor_sync(0xffffffffu, ps, o);
            pd += __shfl_xor_sync(0xffffffffu, pd, o);
        }
        if (r < n) {
            if (FT == 128) {
                if ((cq & 7) == 0) {
                    as_[(long long)r * 2 + (cq >> 3)] = ps;
                    ad_[(long long)r * 2 + (cq >> 3)] = pd;
                }
            } else {
                if (cq == 0) { as_[r] = ps; ad_[r] = pd; }
            }
            __half2 p0 = __float22half2_rn(make_float2(acc[j][0], acc[j][1]));
            __half2 p1 = __float22half2_rn(make_float2(acc[j][2], acc[j][3]));
            __half2 p2 = __float22half2_rn(make_float2(acc[j][4], acc[j][5]));
            __half2 p3 = __float22half2_rn(make_float2(acc[j][6], acc[j][7]));
            uint4 u;
            u.x = *(unsigned*)&p0; u.y = *(unsigned*)&p1;
            u.z = *(unsigned*)&p2; u.w = *(unsigned*)&p3;
            *(uint4*)&h[(long long)r * FT + cq * 8] = u;
        }
    }
}

__device__ __forceinline__ float leaky_exp(float a) {
    a = a > 0.f ? a : 0.2f * a;
    return __expf(a);
}

__device__ __forceinline__ void acc_h16(float4& acc, uint2 u, float w) {
    __half2 a = *reinterpret_cast<const __half2*>(&u.x);
    __half2 b = *reinterpret_cast<const __half2*>(&u.y);
    float2 fa = __half22float2(a), fb = __half22float2(b);
    acc.x += fa.x * w; acc.y += fa.y * w; acc.z += fb.x * w; acc.w += fb.y * w;
}

// ---------------------------------------------------------------------------
// Layer-1 aggregation (CSR): warp per node, F=128 fp16, 2 heads, unroll-4.
// Lane L owns channels [4L, 4L+4) (8 bytes of fp16).  Fuses norm+bias+ELU.
// ---------------------------------------------------------------------------
__global__ __launch_bounds__(256) void agg1_kernel(const int* __restrict__ rowptr,
                                                   const int* __restrict__ col,
                                                   const __half* __restrict__ h,
                                                   const float* __restrict__ as_,
                                                   const float* __restrict__ ad_,
                                                   const float* __restrict__ b1,
                                                   float* __restrict__ o, int n) {
    int i    = (blockIdx.x * blockDim.x + threadIdx.x) >> 5;
    int lane = threadIdx.x & 31;
    if (i >= n) return;
    int head = lane >> 4;
    const uint2* h2p = (const uint2*)h;   // 32 uint2 per 128-half row

    float adv = ad_[i * 2 + head];
    float w = leaky_exp(as_[i * 2 + head] + adv);   // self loop
    float4 acc = make_float4(0.f, 0.f, 0.f, 0.f);
    acc_h16(acc, h2p[(long long)i * 32 + lane], w);
    float den = w;

    int s0 = rowptr[i], s1 = rowptr[i + 1];
    int j = s0;
    for (; j + 3 < s1; j += 4) {
        int sA = col[j], sB = col[j + 1], sC = col[j + 2], sD = col[j + 3];
        float wA = leaky_exp(as_[sA * 2 + head] + adv);
        float wB = leaky_exp(as_[sB * 2 + head] + adv);
        float wC = leaky_exp(as_[sC * 2 + head] + adv);
        float wD = leaky_exp(as_[sD * 2 + head] + adv);
        uint2 uA = h2p[(long long)sA * 32 + lane];
        uint2 uB = h2p[(long long)sB * 32 + lane];
        uint2 uC = h2p[(long long)sC * 32 + lane];
        uint2 uD = h2p[(long long)sD * 32 + lane];
        acc_h16(acc, uA, wA); acc_h16(acc, uB, wB);
        acc_h16(acc, uC, wC); acc_h16(acc, uD, wD);
        den += wA + wB + wC + wD;
    }
    for (; j < s1; j++) {
        int s = col[j];
        w = leaky_exp(as_[s * 2 + head] + adv);
        acc_h16(acc, h2p[(long long)s * 32 + lane], w);
        den += w;
    }
    float inv = 1.f / (den + 1e-16f);
    float4 bv = ((const float4*)b1)[lane];
    float4 v;
    v.x = acc.x * inv + bv.x;
    v.y = acc.y * inv + bv.y;
    v.z = acc.z * inv + bv.z;
    v.w = acc.w * inv + bv.w;
    v.x = v.x > 0.f ? v.x : expm1f(v.x);
    v.y = v.y > 0.f ? v.y : expm1f(v.y);
    v.z = v.z > 0.f ? v.z : expm1f(v.z);
    v.w = v.w > 0.f ? v.w : expm1f(v.w);
    ((float4*)o)[(long long)i * 32 + lane] = v;
}

// ---------------------------------------------------------------------------
// Layer-2 aggregation (CSR): warp per node, F=64 fp16, 1 head, 2 half-warps.
// ---------------------------------------------------------------------------
__global__ __launch_bounds__(256) void agg2_kernel(const int* __restrict__ rowptr,
                                                   const int* __restrict__ col,
                                                   const __half* __restrict__ h,
                                                   const float* __restrict__ as_,
                                                   const float* __restrict__ ad_,
                                                   const float* __restrict__ b2,
                                                   float* __restrict__ o, int n) {
    int i    = (blockIdx.x * blockDim.x + threadIdx.x) >> 5;
    int lane = threadIdx.x & 31;
    if (i >= n) return;
    int sub = lane >> 4, ln = lane & 15;
    const uint2* h2p = (const uint2*)h;   // 16 uint2 per 64-half row

    float adv = ad_[i];
    float4 acc = make_float4(0.f, 0.f, 0.f, 0.f);
    float den = 0.f;
    if (sub == 0) {  // self loop
        float w = leaky_exp(as_[i] + adv);
        acc_h16(acc, h2p[(long long)i * 16 + ln], w);
        den = w;
    }
    int s0 = rowptr[i], s1 = rowptr[i + 1];
    int j = s0 + sub;
    for (; j + 2 < s1; j += 4) {
        int sA = col[j], sB = col[j + 2];
        float wA = leaky_exp(as_[sA] + adv);
        float wB = leaky_exp(as_[sB] + adv);
        uint2 uA = h2p[(long long)sA * 16 + ln];
        uint2 uB = h2p[(long long)sB * 16 + ln];
        acc_h16(acc, uA, wA); acc_h16(acc, uB, wB);
        den += wA + wB;
    }
    for (; j < s1; j += 2) {
        int s = col[j];
        float w = leaky_exp(as_[s] + adv);
        acc_h16(acc, h2p[(long long)s * 16 + ln], w);
        den += w;
    }
    acc.x += __shfl_xor_sync(0xffffffffu, acc.x, 16);
    acc.y += __shfl_xor_sync(0xffffffffu, acc.y, 16);
    acc.z += __shfl_xor_sync(0xffffffffu, acc.z, 16);
    acc.w += __shfl_xor_sync(0xffffffffu, acc.w, 16);
    den   += __shfl_xor_sync(0xffffffffu, den, 16);
    if (sub == 0) {
        float inv = 1.f / (den + 1e-16f);
        float4 bv = ((const float4*)b2)[ln];
        float4 v;
        v.x = acc.x * inv + bv.x;
        v.y = acc.y * inv + bv.y;
        v.z = acc.z * inv + bv.z;
        v.w = acc.w * inv + bv.w;
        v.x = v.x > 0.f ? v.x : expm1f(v.x);
        v.y = v.y > 0.f ? v.y : expm1f(v.y);
        v.z = v.z > 0.f ? v.z : expm1f(v.z);
        v.w = v.w > 0.f ? v.w : expm1f(v.w);
        ((float4*)o)[(long long)i * 16 + ln] = v;
    }
}

// ---------------------------------------------------------------------------
// Final linear(64->16) + sigmoid.  16 nodes per block.
// ---------------------------------------------------------------------------
__global__ __launch_bounds__(256) void final_kernel(const float* __restrict__ o2,
                                                    const float* __restrict__ lw,
                                                    const float* __restrict__ lb,
                                                    float* __restrict__ out, int n) {
    __shared__ float lwsm[64 * 16];
    __shared__ float lbsm[16];
    __shared__ float o2sm[16 * 64];
    int tid = threadIdx.x;
    for (int i = tid; i < 1024; i += 256) lwsm[i] = lw[i];
    if (tid < 16) lbsm[tid] = lb[tid];

    int nb = blockIdx.x * 16;
    for (int t = tid; t < 16 * 64; t += 256) {
        int node = nb + (t >> 6);
        o2sm[t] = (node < n) ? o2[(long long)node * 64 + (t & 63)] : 0.f;
    }
    __syncthreads();

    int node = nb + (tid >> 4);
    int c = tid & 15;
    if (node < n) {
        float s = lbsm[c];
        const float* ov = &o2sm[(tid >> 4) << 6];
#pragma unroll
        for (int k = 0; k < 64; k++) s += ov[k] * lwsm[k * 16 + c];
        out[(long long)node * 16 + c] = 1.f / (1.f + __expf(-s));
    }
}

// ---------------------------------------------------------------------------
extern "C" void kernel_launch(void* const* d_in, const int* in_sizes, int n_in,
                              void* d_out, int out_size)
{
    const float*     x     = (const float*)d_in[0];
    const long long* ei    = (const long long*)d_in[1];
    const float*     W1    = (const float*)d_in[2];
    const float*     asrc1 = (const float*)d_in[3];
    const float*     adst1 = (const float*)d_in[4];
    const float*     b1    = (const float*)d_in[5];
    const float*     W2    = (const float*)d_in[6];
    const float*     asrc2 = (const float*)d_in[7];
    const float*     adst2 = (const float*)d_in[8];
    const float*     b2    = (const float*)d_in[9];
    const float*     lw    = (const float*)d_in[10];
    const float*     lb    = (const float*)d_in[11];

    int n = in_sizes[0] / 128;
    int E = in_sizes[1] / 2;

    __half *h1, *h2;
    float *as1, *ad1, *x2, *as2, *ad2, *o2;
    int *deg, *rowptr, *cursor, *col, *bsum, *boff;
    cudaGetSymbolAddress((void**)&h1,     g_h1);
    cudaGetSymbolAddress((void**)&as1,    g_as1);
    cudaGetSymbolAddress((void**)&ad1,    g_ad1);
    cudaGetSymbolAddress((void**)&x2,     g_x2);
    cudaGetSymbolAddress((void**)&h2,     g_h2);
    cudaGetSymbolAddress((void**)&as2,    g_as2);
    cudaGetSymbolAddress((void**)&ad2,    g_ad2);
    cudaGetSymbolAddress((void**)&o2,     g_o2);
    cudaGetSymbolAddress((void**)&deg,    g_deg);
    cudaGetSymbolAddress((void**)&rowptr, g_rowptr);
    cudaGetSymbolAddress((void**)&cursor, g_cursor);
    cudaGetSymbolAddress((void**)&col,    g_col);
    cudaGetSymbolAddress((void**)&bsum,   g_bsum);
    cudaGetSymbolAddress((void**)&boff,   g_boff);

    // One-time side stream + fork/join events (reused; no device memory).
    static cudaStream_t s_side = nullptr;
    static cudaEvent_t  s_fork = nullptr, s_join = nullptr;
    if (s_side == nullptr) {
        cudaStreamCreateWithFlags(&s_side, cudaStreamNonBlocking);
        cudaEventCreateWithFlags(&s_fork, cudaEventDisableTiming);
        cudaEventCreateWithFlags(&s_join, cudaEventDisableTiming);
    }

    int nb = (n + SCAN_TILE - 1) / SCAN_TILE;

    // Fork: CSR build on side stream, GEMM1 on main stream.
    cudaEventRecord(s_fork, 0);
    cudaStreamWaitEvent(s_side, s_fork, 0);

    zero_deg_kernel<<<(n + 255) / 256, 256, 0, s_side>>>(deg, n, ei, E);
    hist_kernel<<<(E + 255) / 256, 256, 0, s_side>>>(ei, deg, E);
    scan1_kernel<<<nb, 256, 0, s_side>>>(deg, bsum, n);
    scan2_kernel<<<1, 64, 0, s_side>>>(bsum, boff, nb);
    scan3_kernel<<<nb, 256, 0, s_side>>>(deg, boff, rowptr, cursor, n, E);
    scatter_kernel<<<(E + 255) / 256, 256, 0, s_side>>>(ei, cursor, col, E);

    gemm_att_kernel<128><<<(n + 127) / 128, 256>>>(x, W1, asrc1, adst1, h1, as1, ad1, n);

    // Join before aggregation.
    cudaEventRecord(s_join, s_side);
    cudaStreamWaitEvent(0, s_join, 0);

    agg1_kernel<<<(n * 32 + 255) / 256, 256>>>(rowptr, col, h1, as1, ad1, b1, x2, n);
    gemm_att_kernel<64><<<(n + 127) / 128, 256>>>(x2, W2, asrc2, adst2, h2, as2, ad2, n);
    agg2_kernel<<<(n * 32 + 255) / 256, 256>>>(rowptr, col, h2, as2, ad2, b2, o2, n);
    final_kernel<<<(n + 15) / 16, 256>>>(o2, lw, lb, (float*)d_out, n);
}